// round 1
// baseline (speedup 1.0000x reference)
#include <cuda_runtime.h>
#include <math.h>

#define BB   4
#define CC   256
#define NSP  4096            // 64*64 spatial positions
#define EPSN 2.220446049250313e-16f

// ---------------- scratch (device globals; no allocation in kernel_launch) ---
__device__ float g_ymean[BB * CC];
__device__ float g_rnx[BB * NSP];
__device__ float g_rny[BB * NSP];
__device__ float g_Xn[BB * CC * NSP];
__device__ float g_Yn[BB * CC * NSP];
__device__ float g_S[(size_t)BB * NSP * NSP];      // 256 MB similarity matrix
__device__ float g_maxA[BB * NSP];

// ---------------- fast exp: FFMA-only (avoid MUFU bottleneck: 67M exps) ------
__device__ __forceinline__ float fexp(float x) {
    x = fmaxf(x, -80.0f);                      // guard range (result ~0 anyway)
    float y = x * 1.44269504088896341f;        // x / ln2
    float r = rintf(y);
    float t = (y - r) * 0.69314718055994531f;  // t in [-0.3466, 0.3466]
    // e^t, degree-5 Taylor (abs err ~2.4e-6 on this range)
    float p = fmaf(t, 8.3333333e-3f, 4.1666667e-2f);
    p = fmaf(t, p, 1.6666667e-1f);
    p = fmaf(t, p, 5.0e-1f);
    p = fmaf(t, p, 1.0f);
    p = fmaf(t, p, 1.0f);
    float sc = __int_as_float(((int)r + 127) << 23);   // 2^r (r in [-116, 1])
    return p * sc;
}

// ---------------- 1) per-channel spatial mean of Y ---------------------------
__global__ void k_mean(const float* __restrict__ Y) {
    int bc = blockIdx.x;
    int tid = threadIdx.x;
    const float* p = Y + (size_t)bc * NSP;
    float s = 0.0f;
#pragma unroll
    for (int j = 0; j < 16; j++) s += p[tid + j * 256];
    __shared__ float red[256];
    red[tid] = s;
    __syncthreads();
    for (int off = 128; off > 0; off >>= 1) {
        if (tid < off) red[tid] += red[tid + off];
        __syncthreads();
    }
    if (tid == 0) g_ymean[bc] = red[0] * (1.0f / NSP);
}

// ---------------- 2) per-position inverse channel-L2 norms -------------------
__global__ void k_norm(const float* __restrict__ X, const float* __restrict__ Y) {
    int b = blockIdx.y;
    int n = blockIdx.x * 256 + threadIdx.x;
    __shared__ float sm[CC];
    sm[threadIdx.x] = g_ymean[b * CC + threadIdx.x];
    __syncthreads();
    const float* px = X + (size_t)b * CC * NSP + n;
    const float* py = Y + (size_t)b * CC * NSP + n;
    float sx = 0.0f, sy = 0.0f;
#pragma unroll 8
    for (int c = 0; c < CC; c++) {
        float m = sm[c];
        float xv = px[(size_t)c * NSP] - m;
        float yv = py[(size_t)c * NSP] - m;
        sx = fmaf(xv, xv, sx);
        sy = fmaf(yv, yv, sy);
    }
    g_rnx[b * NSP + n] = 1.0f / (sqrtf(sx) + EPSN);
    g_rny[b * NSP + n] = 1.0f / (sqrtf(sy) + EPSN);
}

// ---------------- 3) write centered+normalized features ----------------------
__global__ void k_write(const float* __restrict__ X, const float* __restrict__ Y) {
    int idx = blockIdx.x * 256 + threadIdx.x;        // 0 .. 4*256*4096-1
    int b = idx >> 20;
    int c = (idx >> 12) & 255;
    int n = idx & 4095;
    float m = g_ymean[(b << 8) + c];
    g_Xn[idx] = (X[idx] - m) * g_rnx[(b << 12) + n];
    g_Yn[idx] = (Y[idx] - m) * g_rny[(b << 12) + n];
}

// ---------------- 4) S[b,n,m] = sum_c Xn[b,c,n] * Yn[b,c,m] ------------------
// 128x128 block tile, 8x8 per-thread micro-tile, K-tiles of 8.
__global__ void __launch_bounds__(256, 2) k_gemm() {
    int b  = blockIdx.z;
    int n0 = blockIdx.y * 128;   // row tile (X positions)
    int m0 = blockIdx.x * 128;   // col tile (Y positions)
    const float* A = g_Xn + (size_t)b * CC * NSP;    // [256][4096], k-major
    const float* Bm = g_Yn + (size_t)b * CC * NSP;

    __shared__ __align__(16) float As[8][128];
    __shared__ __align__(16) float Bs[8][128];

    int tid = threadIdx.x;
    int lk = tid >> 5;                // 0..7 (k row within tile)
    int lv = (tid & 31) << 2;         // 0,4,...,124
    int ty = tid >> 4;                // 0..15 -> row group
    int tx = tid & 15;                // 0..15 -> col group

    float acc[8][8];
#pragma unroll
    for (int i = 0; i < 8; i++)
#pragma unroll
        for (int j = 0; j < 8; j++) acc[i][j] = 0.0f;

    for (int k0 = 0; k0 < CC; k0 += 8) {
        float4 av = *(const float4*)(A  + (size_t)(k0 + lk) * NSP + n0 + lv);
        float4 bv = *(const float4*)(Bm + (size_t)(k0 + lk) * NSP + m0 + lv);
        *(float4*)&As[lk][lv] = av;
        *(float4*)&Bs[lk][lv] = bv;
        __syncthreads();
#pragma unroll
        for (int k = 0; k < 8; k++) {
            float a[8], bb[8];
            *(float4*)&a[0]  = *(const float4*)&As[k][ty * 8];
            *(float4*)&a[4]  = *(const float4*)&As[k][ty * 8 + 4];
            *(float4*)&bb[0] = *(const float4*)&Bs[k][tx * 8];
            *(float4*)&bb[4] = *(const float4*)&Bs[k][tx * 8 + 4];
#pragma unroll
            for (int i = 0; i < 8; i++)
#pragma unroll
                for (int j = 0; j < 8; j++) acc[i][j] = fmaf(a[i], bb[j], acc[i][j]);
        }
        __syncthreads();
    }

    float* Sp = g_S + (size_t)b * NSP * NSP + (size_t)(n0 + ty * 8) * NSP + (m0 + tx * 8);
#pragma unroll
    for (int i = 0; i < 8; i++) {
        *(float4*)(Sp + (size_t)i * NSP)     = make_float4(acc[i][0], acc[i][1], acc[i][2], acc[i][3]);
        *(float4*)(Sp + (size_t)i * NSP + 4) = make_float4(acc[i][4], acc[i][5], acc[i][6], acc[i][7]);
    }
}

// ---------------- 5) per-row: smax -> sum_w -> maxA --------------------------
__global__ void k_reduce() {
    int row = blockIdx.x;            // 0 .. B*NSP-1
    int tid = threadIdx.x;
    const float* p = g_S + (size_t)row * NSP;
    float s[16];
    float mx = -1e30f;
#pragma unroll
    for (int j = 0; j < 16; j++) {
        s[j] = p[tid + j * 256];
        mx = fmaxf(mx, s[j]);
    }
    __shared__ float red[256];
    red[tid] = mx;
    __syncthreads();
    for (int off = 128; off > 0; off >>= 1) {
        if (tid < off) red[tid] = fmaxf(red[tid], red[tid + off]);
        __syncthreads();
    }
    float smax = red[0];
    __syncthreads();
    // d = 1 - s; dmin = 1 - smax; c = dmin + 0.001
    // exponent = (1 - d/c)/0.1 = (s - smax + 0.001) * (10/c)
    float c = 1.001f - smax;
    float kk = 10.0f / c;
    float sum = 0.0f;
#pragma unroll
    for (int j = 0; j < 16; j++) sum += fexp((s[j] - smax + 0.001f) * kk);
    red[tid] = sum;
    __syncthreads();
    for (int off = 128; off > 0; off >>= 1) {
        if (tid < off) red[tid] += red[tid + off];
        __syncthreads();
    }
    if (tid == 0) g_maxA[row] = fexp(0.001f * kk) / red[0];
}

// ---------------- 6) CX = mean_n maxA; loss = -log(CX) -----------------------
__global__ void k_final(float* __restrict__ out) {
    int b = blockIdx.x;
    int tid = threadIdx.x;
    float s = 0.0f;
#pragma unroll
    for (int j = 0; j < 16; j++) s += g_maxA[b * NSP + tid + j * 256];
    __shared__ float red[256];
    red[tid] = s;
    __syncthreads();
    for (int off = 128; off > 0; off >>= 1) {
        if (tid < off) red[tid] += red[tid + off];
        __syncthreads();
    }
    if (tid == 0) out[b] = -logf(red[0] * (1.0f / NSP));
}

// ---------------- launch ------------------------------------------------------
extern "C" void kernel_launch(void* const* d_in, const int* in_sizes, int n_in,
                              void* d_out, int out_size) {
    const float* X = (const float*)d_in[0];
    const float* Y = (const float*)d_in[1];
    float* out = (float*)d_out;

    k_mean<<<BB * CC, 256>>>(Y);
    k_norm<<<dim3(NSP / 256, BB), 256>>>(X, Y);
    k_write<<<(BB * CC * NSP) / 256, 256>>>(X, Y);
    k_gemm<<<dim3(NSP / 128, NSP / 128, BB), 256>>>();
    k_reduce<<<BB * NSP, 256>>>();
    k_final<<<BB, 256>>>(out);
}

// round 3
// speedup vs baseline: 2.6513x; 2.6513x over previous
#include <cuda_runtime.h>
#include <math.h>
#include <stdint.h>

#define BB   4
#define CC   256
#define NSP  4096
#define EPSN 2.220446049250313e-16f

// ------------------------- device scratch ------------------------------------
__device__ float g_ymean[BB * CC];
__device__ float g_rnx[BB * NSP];
__device__ float g_rny[BB * NSP];
// [b][n][c'] centered+normalized, tf32-rounded, K-permuted within 32-chunks
__device__ float g_Xt[(size_t)BB * NSP * CC];
__device__ float g_Yt[(size_t)BB * NSP * CC];
__device__ float g_S[(size_t)BB * NSP * NSP];   // 256 MB similarity
__device__ float g_maxA[BB * NSP];

// ------------------------- helpers -------------------------------------------
__device__ __forceinline__ float to_tf32(float x) {
    uint32_t u;
    asm("cvt.rna.tf32.f32 %0, %1;" : "=r"(u) : "f"(x));
    return __uint_as_float(u);
}
#define CP_ASYNC16(dst, src) \
    asm volatile("cp.async.ca.shared.global [%0], [%1], 16;" :: "r"(dst), "l"(src))
#define CP_COMMIT() asm volatile("cp.async.commit_group;")
#define CP_WAIT(n)  asm volatile("cp.async.wait_group %0;" :: "n"(n))

__device__ __forceinline__ uint32_t smem_u32(const void* p) {
    uint32_t a;
    asm("{ .reg .u64 t; cvta.to.shared.u64 t, %1; cvt.u32.u64 %0, t; }" : "=r"(a) : "l"(p));
    return a;
}
__device__ __forceinline__ void mma_tf32(float* c, const uint32_t* a, const uint32_t* b) {
    asm volatile(
        "mma.sync.aligned.m16n8k8.row.col.f32.tf32.tf32.f32 "
        "{%0,%1,%2,%3}, {%4,%5,%6,%7}, {%8,%9}, {%0,%1,%2,%3};"
        : "+f"(c[0]), "+f"(c[1]), "+f"(c[2]), "+f"(c[3])
        : "r"(a[0]), "r"(a[1]), "r"(a[2]), "r"(a[3]), "r"(b[0]), "r"(b[1]));
}

// fast exp (FFMA-only)
__device__ __forceinline__ float fexp(float x) {
    x = fmaxf(x, -80.0f);
    float y = x * 1.44269504088896341f;
    float r = rintf(y);
    float t = (y - r) * 0.69314718055994531f;
    float p = fmaf(t, 8.3333333e-3f, 4.1666667e-2f);
    p = fmaf(t, p, 1.6666667e-1f);
    p = fmaf(t, p, 5.0e-1f);
    p = fmaf(t, p, 1.0f);
    p = fmaf(t, p, 1.0f);
    return p * __int_as_float(((int)r + 127) << 23);
}

// ------------------------- 1) per-channel spatial mean of Y ------------------
__global__ void k_mean(const float* __restrict__ Y) {
    int bc = blockIdx.x, tid = threadIdx.x;
    const float* p = Y + (size_t)bc * NSP;
    float s = 0.0f;
#pragma unroll
    for (int j = 0; j < 16; j++) s += p[tid + j * 256];
    __shared__ float red[256];
    red[tid] = s; __syncthreads();
    for (int off = 128; off > 0; off >>= 1) {
        if (tid < off) red[tid] += red[tid + off];
        __syncthreads();
    }
    if (tid == 0) g_ymean[bc] = red[0] * (1.0f / NSP);
}

// ------------------------- 2) per-position inverse L2 norms ------------------
__global__ void k_norm(const float* __restrict__ X, const float* __restrict__ Y) {
    int b = blockIdx.y;
    int n = blockIdx.x * 256 + threadIdx.x;
    __shared__ float sm[CC];
    sm[threadIdx.x] = g_ymean[b * CC + threadIdx.x];
    __syncthreads();
    const float* px = X + (size_t)b * CC * NSP + n;
    const float* py = Y + (size_t)b * CC * NSP + n;
    float sx = 0.0f, sy = 0.0f;
#pragma unroll 8
    for (int c = 0; c < CC; c++) {
        float m = sm[c];
        float xv = px[(size_t)c * NSP] - m;
        float yv = py[(size_t)c * NSP] - m;
        sx = fmaf(xv, xv, sx);
        sy = fmaf(yv, yv, sy);
    }
    g_rnx[b * NSP + n] = 1.0f / (sqrtf(sx) + EPSN);
    g_rny[b * NSP + n] = 1.0f / (sqrtf(sy) + EPSN);
}

// --------- 3) center+normalize+transpose to [n][c], tf32-round, K-permute ----
// Within each 32-wide K-chunk, column k goes to kp = (k%4)*8 + k/4, so that a
// thread's mma fragment elements for all 4 k-steps are 8 contiguous floats.
__global__ void k_writeT(const float* __restrict__ X, const float* __restrict__ Y) {
    __shared__ float tx[32][33], ty[32][33];
    int b = blockIdx.z;
    int c0 = blockIdx.y * 32, n0 = blockIdx.x * 32;
    int lx = threadIdx.x, ly = threadIdx.y;   // 32 x 8
#pragma unroll
    for (int j = 0; j < 4; j++) {
        int c = c0 + ly + j * 8;
        float m = g_ymean[b * CC + c];
        size_t src = ((size_t)(b * CC + c) << 12) + n0 + lx;
        tx[ly + j * 8][lx] = X[src] - m;
        ty[ly + j * 8][lx] = Y[src] - m;
    }
    __syncthreads();
    int c = c0 + lx;
    int cp = (c & ~31) | (((c & 3) << 3) | ((c & 31) >> 2));
#pragma unroll
    for (int j = 0; j < 4; j++) {
        int n = n0 + ly + j * 8;
        size_t dst = ((size_t)((b << 12) + n)) * CC + cp;
        g_Xt[dst] = to_tf32(tx[lx][ly + j * 8] * g_rnx[(b << 12) + n]);
        g_Yt[dst] = to_tf32(ty[lx][ly + j * 8] * g_rny[(b << 12) + n]);
    }
}

// ------------------------- 4) tf32 mma.sync GEMM -----------------------------
// Block 128x128, 8 warps (2m x 4n) of 64x32, BK=32, cp.async double buffer.
// smem tiles: [128 rows][32 floats = 8x16B chunks], chunk swizzled by row&7.
#define TILE_B   16384          // bytes per 128x32 f32 tile
#define SMA(st)  ((st) * TILE_B)
#define SMB(st)  (2 * TILE_B + (st) * TILE_B)
#define SM_TOT   (4 * TILE_B)   // 64 KB

__global__ void __launch_bounds__(256) k_gemm_mma() {
    extern __shared__ char sm[];
    uint32_t sb = smem_u32(sm);
    int tid = threadIdx.x;
    int l = tid & 31, w = tid >> 5;
    int warpM = w >> 2, warpN = w & 3;
    int b = blockIdx.z;
    int n0 = blockIdx.y * 128, m0 = blockIdx.x * 128;

    const char* Ab = (const char*)(g_Xt + ((size_t)((b << 12) + n0)) * CC);
    const char* Bb = (const char*)(g_Yt + ((size_t)((b << 12) + m0)) * CC);

    int lr = tid >> 3;          // 0..31: row within 32-row pass
    int lc = tid & 7;           // 16B chunk index

    float acc[4][4][4];
#pragma unroll
    for (int i = 0; i < 4; i++)
#pragma unroll
        for (int j = 0; j < 4; j++)
#pragma unroll
            for (int q = 0; q < 4; q++) acc[i][j][q] = 0.0f;

    // --- async load of one K-chunk into stage st ---
    auto load = [&](int kc, int st) {
#pragma unroll
        for (int it = 0; it < 4; it++) {
            int row = lr + it * 32;
            uint32_t sw = (uint32_t)((lc ^ (row & 7)) << 4);
            CP_ASYNC16(sb + SMA(st) + row * 128 + sw, Ab + (size_t)row * 1024 + kc * 128 + lc * 16);
            CP_ASYNC16(sb + SMB(st) + row * 128 + sw, Bb + (size_t)row * 1024 + kc * 128 + lc * 16);
        }
    };

    load(0, 0); CP_COMMIT();

    for (int kc = 0; kc < 8; kc++) {
        int st = kc & 1;
        if (kc + 1 < 8) { load(kc + 1, st ^ 1); CP_COMMIT(); }
        if (kc + 1 < 8) { CP_WAIT(1); } else { CP_WAIT(0); }
        __syncthreads();

        // fragment loads: all 4 k-steps at once (K-permuted layout)
        uint32_t Af[4][2][8];   // [mi][row half][k-pos]
        uint32_t Bf[4][8];      // [ni][k-pos]
        int cbase = (l & 3) << 1;     // even chunk index
#pragma unroll
        for (int mi = 0; mi < 4; mi++) {
#pragma unroll
            for (int h = 0; h < 2; h++) {
                int r = warpM * 64 + mi * 16 + (l >> 2) + h * 8;
                uint32_t ro = sb + SMA(st) + r * 128;
                *(uint4*)&Af[mi][h][0] = *(const uint4*)(sm + (ro - sb) + (((cbase)     ^ (r & 7)) << 4));
                *(uint4*)&Af[mi][h][4] = *(const uint4*)(sm + (ro - sb) + (((cbase + 1) ^ (r & 7)) << 4));
            }
        }
#pragma unroll
        for (int ni = 0; ni < 4; ni++) {
            int r = warpN * 32 + ni * 8 + (l >> 2);
            uint32_t ro = SMB(st) + r * 128;
            *(uint4*)&Bf[ni][0] = *(const uint4*)(sm + ro + (((cbase)     ^ (r & 7)) << 4));
            *(uint4*)&Bf[ni][4] = *(const uint4*)(sm + ro + (((cbase + 1) ^ (r & 7)) << 4));
        }

#pragma unroll
        for (int j = 0; j < 4; j++) {
#pragma unroll
            for (int mi = 0; mi < 4; mi++) {
                uint32_t a[4] = { Af[mi][0][2*j], Af[mi][1][2*j],
                                  Af[mi][0][2*j+1], Af[mi][1][2*j+1] };
#pragma unroll
                for (int ni = 0; ni < 4; ni++) {
                    uint32_t bb[2] = { Bf[ni][2*j], Bf[ni][2*j+1] };
                    mma_tf32(acc[mi][ni], a, bb);
                }
            }
        }
        __syncthreads();
    }

    // --- epilogue: write S ---
    float* Sp = g_S + (size_t)b * NSP * NSP;
#pragma unroll
    for (int mi = 0; mi < 4; mi++) {
        int r = n0 + warpM * 64 + mi * 16 + (l >> 2);
#pragma unroll
        for (int ni = 0; ni < 4; ni++) {
            int cg = m0 + warpN * 32 + ni * 8 + ((l & 3) << 1);
            *(float2*)(Sp + (size_t)r * NSP + cg)       = make_float2(acc[mi][ni][0], acc[mi][ni][1]);
            *(float2*)(Sp + (size_t)(r + 8) * NSP + cg) = make_float2(acc[mi][ni][2], acc[mi][ni][3]);
        }
    }
}

// ------------------------- 5) per-row: smax -> sum_w -> maxA -----------------
__global__ void k_reduce() {
    int row = blockIdx.x, tid = threadIdx.x;
    const float* p = g_S + (size_t)row * NSP;
    float s[16], mx = -1e30f;
#pragma unroll
    for (int j = 0; j < 16; j++) { s[j] = p[tid + j * 256]; mx = fmaxf(mx, s[j]); }
    __shared__ float red[256];
    red[tid] = mx; __syncthreads();
    for (int off = 128; off > 0; off >>= 1) {
        if (tid < off) red[tid] = fmaxf(red[tid], red[tid + off]);
        __syncthreads();
    }
    float smax = red[0];
    __syncthreads();
    float kk = 10.0f / (1.001f - smax);
    float sum = 0.0f;
#pragma unroll
    for (int j = 0; j < 16; j++) sum += fexp((s[j] - smax + 0.001f) * kk);
    red[tid] = sum; __syncthreads();
    for (int off = 128; off > 0; off >>= 1) {
        if (tid < off) red[tid] += red[tid + off];
        __syncthreads();
    }
    if (tid == 0) g_maxA[row] = fexp(0.001f * kk) / red[0];
}

// ------------------------- 6) loss -------------------------------------------
__global__ void k_final(float* __restrict__ out) {
    int b = blockIdx.x, tid = threadIdx.x;
    float s = 0.0f;
#pragma unroll
    for (int j = 0; j < 16; j++) s += g_maxA[b * NSP + tid + j * 256];
    __shared__ float red[256];
    red[tid] = s; __syncthreads();
    for (int off = 128; off > 0; off >>= 1) {
        if (tid < off) red[tid] += red[tid + off];
        __syncthreads();
    }
    if (tid == 0) out[b] = -logf(red[0] * (1.0f / NSP));
}

// ------------------------- launch --------------------------------------------
extern "C" void kernel_launch(void* const* d_in, const int* in_sizes, int n_in,
                              void* d_out, int out_size) {
    const float* X = (const float*)d_in[0];
    const float* Y = (const float*)d_in[1];
    float* out = (float*)d_out;

    cudaFuncSetAttribute(k_gemm_mma, cudaFuncAttributeMaxDynamicSharedMemorySize, SM_TOT);

    k_mean<<<BB * CC, 256>>>(Y);
    k_norm<<<dim3(NSP / 256, BB), 256>>>(X, Y);
    k_writeT<<<dim3(NSP / 32, CC / 32, BB), dim3(32, 8)>>>(X, Y);
    k_gemm_mma<<<dim3(NSP / 128, NSP / 128, BB), 256, SM_TOT>>>();
    k_reduce<<<BB * NSP, 256>>>();
    k_final<<<BB, 256>>>(out);
}